// round 8
// baseline (speedup 1.0000x reference)
#include <cuda_runtime.h>
#include <cstdint>

#define T_ 4096
#define B_ 4
#define C_ 1024
#define MT_ (B_*T_)
#define STAGE_BYTES 65536
#define SMEM_DYN (3*STAGE_BYTES + 1024)

// ---------------- scratch (device globals; no cudaMalloc allowed) ----------
// int8 slice pairs (value = scale * (s0*128 + s1))
__device__ __align__(16) char g_xq0[(size_t)MT_*C_], g_xq1[(size_t)MT_*C_];
__device__ __align__(16) char g_wq0[(size_t)4*C_*C_], g_wq1[(size_t)4*C_*C_];
__device__ __align__(16) char g_qq0[(size_t)MT_*C_], g_qq1[(size_t)MT_*C_];
__device__ __align__(16) char g_kq0[(size_t)MT_*C_], g_kq1[(size_t)MT_*C_];
__device__ __align__(16) char g_vq0[(size_t)MT_*C_], g_vq1[(size_t)MT_*C_];   // Vt [B][C][T]
__device__ __align__(16) char g_pq0[(size_t)B_*T_*T_], g_pq1[(size_t)B_*T_*T_]; // u8 slices
__device__ __align__(16) char g_aq0[(size_t)MT_*C_], g_aq1[(size_t)MT_*C_];
// per-row scales
__device__ float g_sx[MT_], g_sw[4*C_], g_sq[MT_], g_sk[MT_], g_sv[B_*C_];
__device__ float g_sp[MT_], g_sa[MT_];
// fp32 staging: Qf @0, Kf @MT*C, Vtf @2*MT*C ; AOf reuses @0
__device__ __align__(16) float g_F[(size_t)3*MT_*C_];
__device__ __align__(16) float g_S[(size_t)B_*T_*T_];

extern __shared__ char dyn_smem[];

// ---------------- helpers ----------------------------------------------------
static __device__ __forceinline__ uint32_t smem_u32(const void* p){
  uint32_t a;
  asm("{ .reg .u64 t; cvta.to.shared.u64 t, %1; cvt.u32.u64 %0, t; }" : "=r"(a) : "l"(p));
  return a;
}
static __device__ __forceinline__ uint32_t swz(uint32_t o){ return o ^ ((o>>3)&0x70u); }

static __device__ __forceinline__ void ldsm4(uint32_t addr,
    uint32_t &r0, uint32_t &r1, uint32_t &r2, uint32_t &r3){
  asm volatile("ldmatrix.sync.aligned.m8n8.x4.shared.b16 {%0,%1,%2,%3}, [%4];"
    : "=r"(r0), "=r"(r1), "=r"(r2), "=r"(r3) : "r"(addr));
}
static __device__ __forceinline__ void imma_ss(int* c, const uint32_t* a, const uint32_t* b){
  asm volatile("mma.sync.aligned.m16n8k32.row.col.s32.s8.s8.s32 "
    "{%0,%1,%2,%3}, {%4,%5,%6,%7}, {%8,%9}, {%0,%1,%2,%3};"
    : "+r"(c[0]), "+r"(c[1]), "+r"(c[2]), "+r"(c[3])
    : "r"(a[0]), "r"(a[1]), "r"(a[2]), "r"(a[3]), "r"(b[0]), "r"(b[1]));
}
static __device__ __forceinline__ void imma_us(int* c, const uint32_t* a, const uint32_t* b){
  asm volatile("mma.sync.aligned.m16n8k32.row.col.s32.u8.s8.s32 "
    "{%0,%1,%2,%3}, {%4,%5,%6,%7}, {%8,%9}, {%0,%1,%2,%3};"
    : "+r"(c[0]), "+r"(c[1]), "+r"(c[2]), "+r"(c[3])
    : "r"(a[0]), "r"(a[1]), "r"(a[2]), "r"(a[3]), "r"(b[0]), "r"(b[1]));
}

// 128x128 int8 tile (16KB) global -> SW128-swizzled smem (256 threads)
static __device__ __forceinline__ void cp_tile8(uint32_t sb,
    const char* __restrict__ g, int ldk){
  const int t = threadIdx.x;
#pragma unroll
  for (int i = 0; i < 4; ++i){
    int q = t + (i<<8);
    int row = q>>3, gr = q&7;
    const char* src = g + (size_t)row*ldk + (gr<<4);
    uint32_t dst = sb + swz((uint32_t)((row<<7)|(gr<<4)));
    asm volatile("cp.async.cg.shared.global [%0], [%1], 16;"
                 :: "r"(dst), "l"(src) : "memory");
  }
}
static __device__ __forceinline__ void cp_stage8(uint32_t st,
    const char* A0, const char* A1, int lda,
    const char* B0, const char* B1, int ldb, int kt){
  cp_tile8(st +     0, A0 + kt, lda);
  cp_tile8(st + 16384, A1 + kt, lda);
  cp_tile8(st + 32768, B0 + kt, ldb);
  cp_tile8(st + 49152, B1 + kt, ldb);
}

// ---- core: hi/mid[128,128] int32 accumulators, 2-slice int8, BK=128 --------
// dot = sa*sb*(16384*hi + 128*mid);  8 warps, warp tile 64x32, 3-stage pipe.
template<bool AU8>
static __device__ __forceinline__ void igemm_core(
    int (&hi)[4][4][4], int (&mid)[4][4][4],
    const char* __restrict__ A0, const char* __restrict__ A1, int lda,
    const char* __restrict__ B0, const char* __restrict__ B1, int ldb, int K)
{
  const uint32_t sb = (smem_u32(dyn_smem) + 1023u) & ~1023u;
  const int tid = threadIdx.x, lane = tid&31, wid = tid>>5;
  const int wm = wid>>2, wn = wid&3;
  const int l7 = lane&7, sel = lane>>3;
  const int a_r = l7 + ((sel&1)<<3), a_g = sel>>1;    // A: rowblk=sel&1, khalf=sel>>1
  const int b_r = l7 + ((sel>>1)<<3), b_g = sel&1;    // B: rowblk=sel>>1, khalf=sel&1

  const int nc = K >> 7;
  cp_stage8(sb, A0, A1, lda, B0, B1, ldb, 0);
  asm volatile("cp.async.commit_group;" ::: "memory");
  cp_stage8(sb + STAGE_BYTES, A0, A1, lda, B0, B1, ldb, 128);
  asm volatile("cp.async.commit_group;" ::: "memory");

  uint32_t st = sb;
  for (int c = 0; c < nc; ++c){
    if (c + 2 < nc){
      int s = (c + 2) % 3;
      cp_stage8(sb + (uint32_t)s*STAGE_BYTES, A0, A1, lda, B0, B1, ldb, (c+2)<<7);
      asm volatile("cp.async.commit_group;" ::: "memory");
      asm volatile("cp.async.wait_group 2;" ::: "memory");
    } else if (c + 1 < nc){
      asm volatile("cp.async.wait_group 1;" ::: "memory");
    } else {
      asm volatile("cp.async.wait_group 0;" ::: "memory");
    }
    __syncthreads();

#pragma unroll
    for (int ks = 0; ks < 4; ++ks){
      uint32_t b0f[4][2], b1f[4][2];
#pragma unroll
      for (int nn2 = 0; nn2 < 2; ++nn2){
        uint32_t bd = swz((uint32_t)(((wn*32 + nn2*16 + b_r)<<7) | (ks*32 + (b_g<<4))));
        uint32_t r0, r1, r2, r3;
        ldsm4(st + 32768 + bd, r0, r1, r2, r3);
        b0f[nn2*2][0]=r0; b0f[nn2*2][1]=r1; b0f[nn2*2+1][0]=r2; b0f[nn2*2+1][1]=r3;
        ldsm4(st + 49152 + bd, r0, r1, r2, r3);
        b1f[nn2*2][0]=r0; b1f[nn2*2][1]=r1; b1f[nn2*2+1][0]=r2; b1f[nn2*2+1][1]=r3;
      }
#pragma unroll
      for (int mm = 0; mm < 4; ++mm){
        uint32_t a0f[4], a1f[4];
        uint32_t ad = swz((uint32_t)(((wm*64 + mm*16 + a_r)<<7) | (ks*32 + (a_g<<4))));
        ldsm4(st +         ad, a0f[0], a0f[1], a0f[2], a0f[3]);
        ldsm4(st + 16384 + ad, a1f[0], a1f[1], a1f[2], a1f[3]);
#pragma unroll
        for (int nn = 0; nn < 4; ++nn){
          if (AU8){
            imma_us(hi[mm][nn],  a0f, b0f[nn]);
            imma_us(mid[mm][nn], a0f, b1f[nn]);
            imma_us(mid[mm][nn], a1f, b0f[nn]);
          } else {
            imma_ss(hi[mm][nn],  a0f, b0f[nn]);
            imma_ss(mid[mm][nn], a0f, b1f[nn]);
            imma_ss(mid[mm][nn], a1f, b0f[nn]);
          }
        }
      }
    }
    if (c + 1 < nc) __syncthreads();
    st += STAGE_BYTES;
    if (st == sb + 3u*STAGE_BYTES) st = sb;
  }
}

static __device__ __forceinline__ float comb(int h, int m){
  return 16384.f*(float)h + 128.f*(float)m;
}

// ---------------- row quantizer: fp32 -> 2x int8 + scale ---------------------
__global__ __launch_bounds__(256) void quant_rows(
    const float* __restrict__ src, char* __restrict__ q0,
    char* __restrict__ q1, float* __restrict__ sc, int rowlen)
{
  const size_t base = (size_t)blockIdx.x * rowlen;
  const int tid = threadIdx.x;
  __shared__ float red[256];
  float mx = 0.f;
  for (int off = tid*4; off < rowlen; off += 1024){
    float4 v = *reinterpret_cast<const float4*>(src + base + off);
    mx = fmaxf(mx, fmaxf(fmaxf(fabsf(v.x), fabsf(v.y)),
                         fmaxf(fabsf(v.z), fabsf(v.w))));
  }
  red[tid] = mx; __syncthreads();
  for (int s = 128; s > 0; s >>= 1){
    if (tid < s) red[tid] = fmaxf(red[tid], red[tid+s]);
    __syncthreads();
  }
  const float m = red[0];
  const float inv = (m > 0.f) ? 16256.f/m : 0.f;
  if (tid == 0) sc[blockIdx.x] = (m > 0.f) ? m*(1.f/16256.f) : 1.f;
  for (int off = tid*4; off < rowlen; off += 1024){
    float4 v = *reinterpret_cast<const float4*>(src + base + off);
    float q[4] = {v.x*inv, v.y*inv, v.z*inv, v.w*inv};
    char c0[4], c1[4];
#pragma unroll
    for (int j = 0; j < 4; ++j){
      int a0 = __float2int_rn(q[j]*0.0078125f);
      int a1 = __float2int_rn(q[j] - 128.f*(float)a0);
      c0[j] = (char)a0; c1[j] = (char)a1;
    }
    *reinterpret_cast<char4*>(q0 + base + off) = make_char4(c0[0],c0[1],c0[2],c0[3]);
    *reinterpret_cast<char4*>(q1 + base + off) = make_char4(c1[0],c1[1],c1[2],c1[3]);
  }
}

// ---------------- GEMM kernels ------------------------------------------------
__global__ __launch_bounds__(256, 1) void qkv_imma()
{
  const int z = blockIdx.z, m0 = blockIdx.y<<7, n0 = blockIdx.x<<7;
  int hi[4][4][4] = {}, mid[4][4][4] = {};
  igemm_core<false>(hi, mid,
      g_xq0 + (size_t)m0*C_, g_xq1 + (size_t)m0*C_, C_,
      g_wq0 + (size_t)z*C_*C_ + (size_t)n0*C_,
      g_wq1 + (size_t)z*C_*C_ + (size_t)n0*C_, C_, C_);

  const int lane = threadIdx.x&31, wid = threadIdx.x>>5;
  const int wm = wid>>2, wn = wid&3;
  const int rb = lane>>2, cb = (lane&3)*2;

  if (z == 2){
    // V: transpose in smem to [c][t] fp32, then coalesced write to Vtf staging
    __syncthreads();
    float* sf = reinterpret_cast<float*>(dyn_smem);   // 128x128 fp32 = 64KB
#pragma unroll
    for (int mm = 0; mm < 4; ++mm)
#pragma unroll
      for (int nn = 0; nn < 4; ++nn){
        const int tl = wm*64 + mm*16 + rb;
        const int cl = wn*32 + nn*8 + cb;
#pragma unroll
        for (int u = 0; u < 4; ++u){
          const int tt = tl + (u>>1)*8;
          const int ccl = cl + (u&1);
          float val = g_sx[m0+tt]*g_sw[2*C_+n0+ccl]*comb(hi[mm][nn][u], mid[mm][nn][u]);
          sf[ccl*128 + tt] = val;
        }
      }
    __syncthreads();
    const int b = m0 >> 12, ml0 = m0 & (T_-1);
    float* vtf = g_F + (size_t)2*MT_*C_;
    for (int i = threadIdx.x; i < 4096; i += 256){
      const int row = i>>5, c4 = i&31;
      reinterpret_cast<float4*>(vtf + (size_t)(b*C_ + n0 + row)*T_ + ml0)[c4] =
          reinterpret_cast<const float4*>(sf + row*128)[c4];
    }
    return;
  }

  float* dst = g_F + (size_t)z*MT_*C_;
#pragma unroll
  for (int mm = 0; mm < 4; ++mm)
#pragma unroll
    for (int nn = 0; nn < 4; ++nn){
      const int r  = m0 + wm*64 + mm*16 + rb;
      const int cc = n0 + wn*32 + nn*8 + cb;
      const float s0 = g_sw[z*C_+cc], s1 = g_sw[z*C_+cc+1];
      const float sr0 = g_sx[r], sr1 = g_sx[r+8];
      const int* h = hi[mm][nn]; const int* md = mid[mm][nn];
      *reinterpret_cast<float2*>(dst + (size_t)r*C_ + cc) =
          make_float2(sr0*s0*comb(h[0],md[0]), sr0*s1*comb(h[1],md[1]));
      *reinterpret_cast<float2*>(dst + (size_t)(r+8)*C_ + cc) =
          make_float2(sr1*s0*comb(h[2],md[2]), sr1*s1*comb(h[3],md[3]));
    }
}

__global__ __launch_bounds__(256, 1) void scores_imma()
{
  if (blockIdx.x > blockIdx.y) return;               // fully-masked tile
  const int bz = blockIdx.z, m0 = blockIdx.y<<7, n0 = blockIdx.x<<7;
  const size_t qb = ((size_t)bz*T_ + m0)*C_;
  const size_t kb = ((size_t)bz*T_ + n0)*C_;
  int hi[4][4][4] = {}, mid[4][4][4] = {};
  igemm_core<false>(hi, mid, g_qq0 + qb, g_qq1 + qb, C_,
                    g_kq0 + kb, g_kq1 + kb, C_, C_);

  const int lane = threadIdx.x&31, wid = threadIdx.x>>5;
  const int wm = wid>>2, wn = wid&3;
  const int rb = lane>>2, cb = (lane&3)*2;
#pragma unroll
  for (int mm = 0; mm < 4; ++mm)
#pragma unroll
    for (int nn = 0; nn < 4; ++nn){
      const int r  = m0 + wm*64 + mm*16 + rb;
      const int cc = n0 + wn*32 + nn*8 + cb;
      const float s0 = g_sk[bz*T_+cc], s1 = g_sk[bz*T_+cc+1];
      const float sr0 = g_sq[bz*T_+r], sr1 = g_sq[bz*T_+r+8];
      const int* h = hi[mm][nn]; const int* md = mid[mm][nn];
      float* p = g_S + ((size_t)bz*T_ + r)*T_ + cc;
      *reinterpret_cast<float2*>(p) =
          make_float2(sr0*s0*comb(h[0],md[0]), sr0*s1*comb(h[1],md[1]));
      *reinterpret_cast<float2*>(p + 8ull*T_) =
          make_float2(sr1*s0*comb(h[2],md[2]), sr1*s1*comb(h[3],md[3]));
    }
}

__global__ __launch_bounds__(256, 1) void pv_imma()
{
  const int bz = blockIdx.z, m0 = blockIdx.y<<7, n0 = blockIdx.x<<7;
  const int K  = m0 + 128;
  const size_t pb = ((size_t)bz*T_ + m0)*T_;
  const size_t vb = ((size_t)bz*C_ + n0)*T_;
  int hi[4][4][4] = {}, mid[4][4][4] = {};
  igemm_core<true>(hi, mid, g_pq0 + pb, g_pq1 + pb, T_,
                   g_vq0 + vb, g_vq1 + vb, T_, K);

  const int lane = threadIdx.x&31, wid = threadIdx.x>>5;
  const int wm = wid>>2, wn = wid&3;
  const int rb = lane>>2, cb = (lane&3)*2;
  float* dst = g_F;                                   // AOf staging @0
#pragma unroll
  for (int mm = 0; mm < 4; ++mm)
#pragma unroll
    for (int nn = 0; nn < 4; ++nn){
      const int r  = m0 + wm*64 + mm*16 + rb;
      const int cc = n0 + wn*32 + nn*8 + cb;
      const float s0 = g_sv[bz*C_+cc], s1 = g_sv[bz*C_+cc+1];
      const float sr0 = g_sp[bz*T_+r], sr1 = g_sp[bz*T_+r+8];
      const int* h = hi[mm][nn]; const int* md = mid[mm][nn];
      *reinterpret_cast<float2*>(dst + ((size_t)bz*T_ + r)*C_ + cc) =
          make_float2(sr0*s0*comb(h[0],md[0]), sr0*s1*comb(h[1],md[1]));
      *reinterpret_cast<float2*>(dst + ((size_t)bz*T_ + r + 8)*C_ + cc) =
          make_float2(sr1*s0*comb(h[2],md[2]), sr1*s1*comb(h[3],md[3]));
    }
}

__global__ __launch_bounds__(256, 1) void out_imma(const float* __restrict__ bo,
                                                   float* __restrict__ out)
{
  const int m0 = blockIdx.y<<7, n0 = blockIdx.x<<7;
  int hi[4][4][4] = {}, mid[4][4][4] = {};
  igemm_core<false>(hi, mid,
      g_aq0 + (size_t)m0*C_, g_aq1 + (size_t)m0*C_, C_,
      g_wq0 + (size_t)3*C_*C_ + (size_t)n0*C_,
      g_wq1 + (size_t)3*C_*C_ + (size_t)n0*C_, C_, C_);

  const int lane = threadIdx.x&31, wid = threadIdx.x>>5;
  const int wm = wid>>2, wn = wid&3;
  const int rb = lane>>2, cb = (lane&3)*2;
#pragma unroll
  for (int mm = 0; mm < 4; ++mm)
#pragma unroll
    for (int nn = 0; nn < 4; ++nn){
      const int r  = m0 + wm*64 + mm*16 + rb;
      const int cc = n0 + wn*32 + nn*8 + cb;
      const float s0 = g_sw[3*C_+cc], s1 = g_sw[3*C_+cc+1];
      const float sr0 = g_sa[r], sr1 = g_sa[r+8];
      const float b0 = bo[cc], b1 = bo[cc+1];
      const int* h = hi[mm][nn]; const int* md = mid[mm][nn];
      *reinterpret_cast<float2*>(out + (size_t)r*C_ + cc) =
          make_float2(sr0*s0*comb(h[0],md[0]) + b0, sr0*s1*comb(h[1],md[1]) + b1);
      *reinterpret_cast<float2*>(out + (size_t)(r+8)*C_ + cc) =
          make_float2(sr1*s0*comb(h[2],md[2]) + b0, sr1*s1*comb(h[3],md[3]) + b1);
    }
}

// ---------------- softmax: mask + scale + u8 quantized P --------------------
__global__ __launch_bounds__(256) void softmax_k()
{
  const int gr = blockIdx.x;                 // 0..MT-1
  const int b  = gr >> 12, r = gr & (T_-1);
  const float* src = g_S + ((size_t)b*T_ + r)*T_;
  char* p0 = g_pq0 + ((size_t)b*T_ + r)*T_;
  char* p1 = g_pq1 + ((size_t)b*T_ + r)*T_;
  const int tid = threadIdx.x;
  const int nv  = r + 1;
  const int kmax = ((r >> 7) + 1) << 7;      // zero-pad to 128 (BK granularity)
  const float scale = 0.03125f;              // 1/sqrt(1024)
  __shared__ float red[256];

  float m = __int_as_float(0xff800000);
  for (int c = tid; c < nv; c += 256) m = fmaxf(m, src[c]);
  red[tid] = m; __syncthreads();
  for (int s = 128; s > 0; s >>= 1){
    if (tid < s) red[tid] = fmaxf(red[tid], red[tid+s]);
    __syncthreads();
  }
  m = red[0]; __syncthreads();

  float sum = 0.f;
  for (int c = tid; c < nv; c += 256) sum += __expf((src[c] - m) * scale);
  red[tid] = sum; __syncthreads();
  for (int s = 128; s > 0; s >>= 1){
    if (tid < s) red[tid] += red[tid+s];
    __syncthreads();
  }
  const float inv = 1.f / red[0];
  if (tid == 0) g_sp[gr] = inv * (1.f/32640.f);   // p = sp*(u0*128 + u1), u8

  for (int c0i = tid*4; c0i < kmax; c0i += 1024){
    char a0[4], a1[4];
#pragma unroll
    for (int j = 0; j < 4; ++j){
      const int c = c0i + j;
      if (c < nv){
        float e = __expf((src[c] - m) * scale);
        float q = e * 32640.f;                      // in [0, 32640]
        int h = (int)(q * 0.0078125f);              // floor, 0..255
        int l = __float2int_rn(q - 128.f*(float)h); // 0..128
        a0[j] = (char)h; a1[j] = (char)l;
      } else { a0[j] = 0; a1[j] = 0; }
    }
    *reinterpret_cast<char4*>(p0 + c0i) = make_char4(a0[0],a0[1],a0[2],a0[3]);
    *reinterpret_cast<char4*>(p1 + c0i) = make_char4(a1[0],a1[1],a1[2],a1[3]);
  }
}

// ---------------- launch ------------------------------------------------------
extern "C" void kernel_launch(void* const* d_in, const int* in_sizes, int n_in,
                              void* d_out, int out_size)
{
  const float* x  = (const float*)d_in[0];
  const float* Wq = (const float*)d_in[1];
  const float* Wk = (const float*)d_in[2];
  const float* Wv = (const float*)d_in[3];
  const float* Wo = (const float*)d_in[4];
  const float* bo = (const float*)d_in[5];
  float* out = (float*)d_out;
  (void)in_sizes; (void)n_in; (void)out_size;

  cudaFuncSetAttribute(qkv_imma,    cudaFuncAttributeMaxDynamicSharedMemorySize, SMEM_DYN);
  cudaFuncSetAttribute(scores_imma, cudaFuncAttributeMaxDynamicSharedMemorySize, SMEM_DYN);
  cudaFuncSetAttribute(pv_imma,     cudaFuncAttributeMaxDynamicSharedMemorySize, SMEM_DYN);
  cudaFuncSetAttribute(out_imma,    cudaFuncAttributeMaxDynamicSharedMemorySize, SMEM_DYN);

  char *xq0,*xq1,*wq0,*wq1,*qq0,*qq1,*kq0,*kq1,*vq0,*vq1,*aq0,*aq1;
  float *sx,*sw,*sq,*sk,*sv,*sa,*Ff;
  cudaGetSymbolAddress((void**)&xq0, g_xq0); cudaGetSymbolAddress((void**)&xq1, g_xq1);
  cudaGetSymbolAddress((void**)&wq0, g_wq0); cudaGetSymbolAddress((void**)&wq1, g_wq1);
  cudaGetSymbolAddress((void**)&qq0, g_qq0); cudaGetSymbolAddress((void**)&qq1, g_qq1);
  cudaGetSymbolAddress((void**)&kq0, g_kq0); cudaGetSymbolAddress((void**)&kq1, g_kq1);
  cudaGetSymbolAddress((void**)&vq0, g_vq0); cudaGetSymbolAddress((void**)&vq1, g_vq1);
  cudaGetSymbolAddress((void**)&aq0, g_aq0); cudaGetSymbolAddress((void**)&aq1, g_aq1);
  cudaGetSymbolAddress((void**)&sx, g_sx);   cudaGetSymbolAddress((void**)&sw, g_sw);
  cudaGetSymbolAddress((void**)&sq, g_sq);   cudaGetSymbolAddress((void**)&sk, g_sk);
  cudaGetSymbolAddress((void**)&sv, g_sv);   cudaGetSymbolAddress((void**)&sa, g_sa);
  cudaGetSymbolAddress((void**)&Ff, g_F);

  const size_t CC = (size_t)C_*C_;
  const size_t MC = (size_t)MT_*C_;

  quant_rows<<<MT_, 256>>>(x,  xq0, xq1, sx, C_);
  quant_rows<<<C_,  256>>>(Wq, wq0,        wq1,        sw,        C_);
  quant_rows<<<C_,  256>>>(Wk, wq0 + CC,   wq1 + CC,   sw + C_,   C_);
  quant_rows<<<C_,  256>>>(Wv, wq0 + 2*CC, wq1 + 2*CC, sw + 2*C_, C_);
  quant_rows<<<C_,  256>>>(Wo, wq0 + 3*CC, wq1 + 3*CC, sw + 3*C_, C_);

  qkv_imma<<<dim3(C_/128, MT_/128, 3), 256, SMEM_DYN>>>();

  quant_rows<<<MT_,   256>>>(Ff,        qq0, qq1, sq, C_);   // Qf
  quant_rows<<<MT_,   256>>>(Ff + MC,   kq0, kq1, sk, C_);   // Kf
  quant_rows<<<B_*C_, 256>>>(Ff + 2*MC, vq0, vq1, sv, T_);   // Vtf

  scores_imma<<<dim3(T_/128, T_/128, B_), 256, SMEM_DYN>>>();
  softmax_k  <<<MT_, 256>>>();
  pv_imma    <<<dim3(C_/128, T_/128, B_), 256, SMEM_DYN>>>();

  quant_rows<<<MT_, 256>>>(Ff, aq0, aq1, sa, C_);            // AOf

  out_imma<<<dim3(C_/128, MT_/128, 1), 256, SMEM_DYN>>>(bo, out);
}

// round 9
// speedup vs baseline: 4.4114x; 4.4114x over previous
#include <cuda_runtime.h>
#include <cuda_fp16.h>
#include <cstdint>

#define T_ 4096
#define B_ 4
#define C_ 1024
#define MT_ (B_*T_)
#define STAGE_BYTES 49152          // Ahi 16KB + Alo 16KB + B 16KB
#define SMEM_DYN (2*STAGE_BYTES + 1024)

// ---------------- scratch (device globals; no cudaMalloc allowed) ----------
__device__ __align__(16) __half g_xh[(size_t)MT_*C_], g_xl[(size_t)MT_*C_];
__device__ __align__(16) __half g_W [(size_t)4*C_*C_];          // single fp16
__device__ __align__(16) __half g_Qh[(size_t)MT_*C_], g_Ql[(size_t)MT_*C_];
__device__ __align__(16) __half g_K [(size_t)MT_*C_];           // single
__device__ __align__(16) __half g_Vt[(size_t)MT_*C_];           // single, [B][C][T]
__device__ __align__(16) float  g_S [(size_t)B_*T_*T_];
__device__ __align__(16) __half g_Ph[(size_t)B_*T_*T_], g_Pl[(size_t)B_*T_*T_];
__device__ __align__(16) __half g_Ah[(size_t)MT_*C_], g_Al[(size_t)MT_*C_];

extern __shared__ char dyn_smem[];

// ---------------- helpers ----------------------------------------------------
static __device__ __forceinline__ uint32_t smem_u32(const void* p){
  uint32_t a;
  asm("{ .reg .u64 t; cvta.to.shared.u64 t, %1; cvt.u32.u64 %0, t; }" : "=r"(a) : "l"(p));
  return a;
}
static __device__ __forceinline__ uint32_t swz(uint32_t o){ return o ^ ((o>>3)&0x70u); }

static __device__ __forceinline__ void ldsm4(uint32_t addr,
    uint32_t &r0, uint32_t &r1, uint32_t &r2, uint32_t &r3){
  asm volatile("ldmatrix.sync.aligned.m8n8.x4.shared.b16 {%0,%1,%2,%3}, [%4];"
    : "=r"(r0), "=r"(r1), "=r"(r2), "=r"(r3) : "r"(addr));
}
static __device__ __forceinline__ void mma16816(float* c,
    const uint32_t* a, const uint32_t* b){
  asm volatile("mma.sync.aligned.m16n8k16.row.col.f32.f16.f16.f32 "
    "{%0,%1,%2,%3}, {%4,%5,%6,%7}, {%8,%9}, {%0,%1,%2,%3};"
    : "+f"(c[0]), "+f"(c[1]), "+f"(c[2]), "+f"(c[3])
    : "r"(a[0]), "r"(a[1]), "r"(a[2]), "r"(a[3]), "r"(b[0]), "r"(b[1]));
}

// 128x64 fp16 tile (16KB) global -> SW128-swizzled smem (256 threads)
static __device__ __forceinline__ void cp_tile(uint32_t sb,
    const __half* __restrict__ g, int ldk){
  const int t = threadIdx.x;
#pragma unroll
  for (int i = 0; i < 4; ++i){
    int q = t + (i<<8);
    int row = q>>3, gr = q&7;
    const __half* src = g + (size_t)row*ldk + (gr<<3);
    uint32_t dst = sb + swz((uint32_t)((row<<7)|(gr<<4)));
    asm volatile("cp.async.cg.shared.global [%0], [%1], 16;"
                 :: "r"(dst), "l"(src) : "memory");
  }
}
static __device__ __forceinline__ void cp_stage(uint32_t st,
    const __half* Ah, const __half* Al, int lda,
    const __half* Bs, int ldb, int kt){
  cp_tile(st +     0, Ah + kt, lda);
  cp_tile(st + 16384, Al + kt, lda);
  cp_tile(st + 32768, Bs + kt, ldb);
}

// ---- core: acc[128,128] += (Ah+Al)[128,K] @ (B[128,K])^T  (fp16 2-pass) -----
// 8 warps: wm = wid>>2 (2 x 64 rows), wn = wid&3 (4 x 32 cols)
static __device__ __forceinline__ void hgemm_core(
    float (&acc)[4][4][4],
    const __half* __restrict__ Ah, const __half* __restrict__ Al, int lda,
    const __half* __restrict__ Bs, int ldb, int K)
{
  const uint32_t sb = (smem_u32(dyn_smem) + 1023u) & ~1023u;
  const int tid = threadIdx.x, lane = tid&31, wid = tid>>5;
  const int wm = wid>>2, wn = wid&3;
  const int l7 = lane&7, sel = lane>>3;
  const int a_r = l7 + ((sel&1)<<3), a_g = sel>>1;
  const int b_r = l7 + ((sel>>1)<<3), b_g = sel&1;

  const int nc = K >> 6;          // >= 2 everywhere in this pipeline
  cp_stage(sb, Ah, Al, lda, Bs, ldb, 0);
  asm volatile("cp.async.commit_group;" ::: "memory");

  for (int c = 0; c < nc; ++c){
    const uint32_t st = sb + (uint32_t)(c&1)*STAGE_BYTES;
    if (c + 1 < nc){
      cp_stage(sb + (uint32_t)((c+1)&1)*STAGE_BYTES, Ah, Al, lda, Bs, ldb, (c+1)<<6);
      asm volatile("cp.async.commit_group;" ::: "memory");
      asm volatile("cp.async.wait_group 1;" ::: "memory");
    } else {
      asm volatile("cp.async.wait_group 0;" ::: "memory");
    }
    __syncthreads();

#pragma unroll
    for (int ks = 0; ks < 4; ++ks){
      uint32_t bf[4][2];
#pragma unroll
      for (int nn2 = 0; nn2 < 2; ++nn2){
        uint32_t bd = swz((uint32_t)(((wn*32 + nn2*16 + b_r)<<7) | ((ks*2 + b_g)<<4)));
        uint32_t r0, r1, r2, r3;
        ldsm4(st + 32768 + bd, r0, r1, r2, r3);
        bf[nn2*2][0]=r0; bf[nn2*2][1]=r1; bf[nn2*2+1][0]=r2; bf[nn2*2+1][1]=r3;
      }
#pragma unroll
      for (int mm = 0; mm < 4; ++mm){
        uint32_t ah[4], al[4];
        uint32_t ad = swz((uint32_t)(((wm*64 + mm*16 + a_r)<<7) | ((ks*2 + a_g)<<4)));
        ldsm4(st +         ad, ah[0], ah[1], ah[2], ah[3]);
        ldsm4(st + 16384 + ad, al[0], al[1], al[2], al[3]);
#pragma unroll
        for (int nn = 0; nn < 4; ++nn){
          mma16816(acc[mm][nn], ah, bf[nn]);
          mma16816(acc[mm][nn], al, bf[nn]);
        }
      }
    }
    if (c + 1 < nc) __syncthreads();
  }
}

static __device__ __forceinline__ void pair_store2(
    __half* H, __half* L, size_t idx, float a, float b){
  __half ah = __float2half_rn(a), bh = __float2half_rn(b);
  __half al = __float2half_rn(a - __half2float(ah));
  __half bl = __float2half_rn(b - __half2float(bh));
  *reinterpret_cast<__half2*>(H + idx) = __halves2half2(ah, bh);
  *reinterpret_cast<__half2*>(L + idx) = __halves2half2(al, bl);
}

// ---------------- input converters ------------------------------------------
__global__ __launch_bounds__(256) void split_x(const float* __restrict__ x){
  size_t i = ((size_t)blockIdx.x*256 + threadIdx.x)*4;
  float4 v = *reinterpret_cast<const float4*>(x + i);
  float f[4] = {v.x, v.y, v.z, v.w};
  __half h[4], l[4];
#pragma unroll
  for (int k = 0; k < 4; ++k){
    h[k] = __float2half_rn(f[k]);
    l[k] = __float2half_rn(f[k] - __half2float(h[k]));
  }
  reinterpret_cast<__half2*>(g_xh + i)[0] = __halves2half2(h[0], h[1]);
  reinterpret_cast<__half2*>(g_xh + i)[1] = __halves2half2(h[2], h[3]);
  reinterpret_cast<__half2*>(g_xl + i)[0] = __halves2half2(l[0], l[1]);
  reinterpret_cast<__half2*>(g_xl + i)[1] = __halves2half2(l[2], l[3]);
}
__global__ __launch_bounds__(256) void conv_w(
    const float* __restrict__ Wq, const float* __restrict__ Wk,
    const float* __restrict__ Wv, const float* __restrict__ Wo)
{
  const int z = blockIdx.y;
  const float* src = (z==0)?Wq:(z==1)?Wk:(z==2)?Wv:Wo;
  size_t i = ((size_t)blockIdx.x*256 + threadIdx.x)*4;
  float4 v = *reinterpret_cast<const float4*>(src + i);
  __half* dst = g_W + (size_t)z*C_*C_ + i;
  reinterpret_cast<__half2*>(dst)[0] = __halves2half2(__float2half_rn(v.x), __float2half_rn(v.y));
  reinterpret_cast<__half2*>(dst)[1] = __halves2half2(__float2half_rn(v.z), __float2half_rn(v.w));
}

// ---------------- GEMM kernels ------------------------------------------------
__global__ __launch_bounds__(256, 2) void qkv_tc()
{
  const int z = blockIdx.z, m0 = blockIdx.y<<7, n0 = blockIdx.x<<7;
  float acc[4][4][4] = {};
  hgemm_core(acc, g_xh + (size_t)m0*C_, g_xl + (size_t)m0*C_, C_,
             g_W + (size_t)z*C_*C_ + (size_t)n0*C_, C_, C_);

  const int lane = threadIdx.x&31, wid = threadIdx.x>>5;
  const int wm = wid>>2, wn = wid&3;
  const int rb = lane>>2, cb = (lane&3)*2;

  if (z == 2){
    // V: transpose in smem to [c][t] fp16, then coalesced writes
    __syncthreads();
    __half* sf = reinterpret_cast<__half*>(dyn_smem);   // 128x128 half = 32KB
#pragma unroll
    for (int mm = 0; mm < 4; ++mm)
#pragma unroll
      for (int nn = 0; nn < 4; ++nn){
        const int tl = wm*64 + mm*16 + rb;
        const int cl = wn*32 + nn*8 + cb;
        const float* a = acc[mm][nn];
#pragma unroll
        for (int u = 0; u < 4; ++u){
          const int tt = tl + (u>>1)*8;
          const int ccl = cl + (u&1);
          sf[ccl*128 + tt] = __float2half_rn(a[u]);
        }
      }
    __syncthreads();
    const int b = m0 >> 12, ml0 = m0 & (T_-1);
    for (int i = threadIdx.x; i < 2048; i += 256){   // 128 rows x 16 uint4
      const int row = i>>4, c4 = i&15;
      reinterpret_cast<uint4*>(g_Vt + (size_t)(b*C_ + n0 + row)*T_ + ml0)[c4] =
          reinterpret_cast<const uint4*>(sf + row*128)[c4];
    }
    return;
  }

#pragma unroll
  for (int mm = 0; mm < 4; ++mm)
#pragma unroll
    for (int nn = 0; nn < 4; ++nn){
      const int r  = m0 + wm*64 + mm*16 + rb;
      const int cc = n0 + wn*32 + nn*8 + cb;
      const float* a = acc[mm][nn];
      size_t base = (size_t)r*C_ + cc;
      if (z == 0){
        pair_store2(g_Qh, g_Ql, base,        a[0], a[1]);
        pair_store2(g_Qh, g_Ql, base + 8*C_, a[2], a[3]);
      } else {
        *reinterpret_cast<__half2*>(g_K + base) =
            __halves2half2(__float2half_rn(a[0]), __float2half_rn(a[1]));
        *reinterpret_cast<__half2*>(g_K + base + 8*C_) =
            __halves2half2(__float2half_rn(a[2]), __float2half_rn(a[3]));
      }
    }
}

__global__ __launch_bounds__(256, 2) void scores_tc()
{
  if (blockIdx.x > blockIdx.y) return;               // fully-masked tile
  const int bz = blockIdx.z, m0 = blockIdx.y<<7, n0 = blockIdx.x<<7;
  const size_t qb = ((size_t)bz*T_ + m0)*C_;
  const size_t kb = ((size_t)bz*T_ + n0)*C_;
  float acc[4][4][4] = {};
  hgemm_core(acc, g_Qh + qb, g_Ql + qb, C_, g_K + kb, C_, C_);

  const int lane = threadIdx.x&31, wid = threadIdx.x>>5;
  const int wm = wid>>2, wn = wid&3;
  const int rb = lane>>2, cb = (lane&3)*2;
#pragma unroll
  for (int mm = 0; mm < 4; ++mm)
#pragma unroll
    for (int nn = 0; nn < 4; ++nn){
      const int r  = m0 + wm*64 + mm*16 + rb;
      const int cc = n0 + wn*32 + nn*8 + cb;
      const float* a = acc[mm][nn];
      float* p = g_S + ((size_t)bz*T_ + r)*T_ + cc;
      *reinterpret_cast<float2*>(p)           = make_float2(a[0], a[1]);
      *reinterpret_cast<float2*>(p + 8ull*T_) = make_float2(a[2], a[3]);
    }
}

__global__ __launch_bounds__(256, 2) void pv_tc()
{
  const int bz = blockIdx.z, m0 = blockIdx.y<<7, n0 = blockIdx.x<<7;
  const int K  = m0 + 128;
  const size_t pb = ((size_t)bz*T_ + m0)*T_;
  const size_t vb = ((size_t)bz*C_ + n0)*T_;
  float acc[4][4][4] = {};
  hgemm_core(acc, g_Ph + pb, g_Pl + pb, T_, g_Vt + vb, T_, K);

  const int lane = threadIdx.x&31, wid = threadIdx.x>>5;
  const int wm = wid>>2, wn = wid&3;
  const int rb = lane>>2, cb = (lane&3)*2;
#pragma unroll
  for (int mm = 0; mm < 4; ++mm)
#pragma unroll
    for (int nn = 0; nn < 4; ++nn){
      const int r  = m0 + wm*64 + mm*16 + rb;
      const int cc = n0 + wn*32 + nn*8 + cb;
      const float* a = acc[mm][nn];
      size_t base = ((size_t)bz*T_ + r)*C_ + cc;
      pair_store2(g_Ah, g_Al, base,        a[0], a[1]);
      pair_store2(g_Ah, g_Al, base + 8*C_, a[2], a[3]);
    }
}

__global__ __launch_bounds__(256, 2) void out_tc(const float* __restrict__ bo,
                                                 float* __restrict__ out)
{
  const int m0 = blockIdx.y<<7, n0 = blockIdx.x<<7;
  float acc[4][4][4] = {};
  hgemm_core(acc, g_Ah + (size_t)m0*C_, g_Al + (size_t)m0*C_, C_,
             g_W + (size_t)3*C_*C_ + (size_t)n0*C_, C_, C_);

  const int lane = threadIdx.x&31, wid = threadIdx.x>>5;
  const int wm = wid>>2, wn = wid&3;
  const int rb = lane>>2, cb = (lane&3)*2;
#pragma unroll
  for (int mm = 0; mm < 4; ++mm)
#pragma unroll
    for (int nn = 0; nn < 4; ++nn){
      const int r  = m0 + wm*64 + mm*16 + rb;
      const int cc = n0 + wn*32 + nn*8 + cb;
      const float* a = acc[mm][nn];
      const float b0 = bo[cc], b1 = bo[cc+1];
      float* p = out + (size_t)r*C_ + cc;
      *reinterpret_cast<float2*>(p)        = make_float2(a[0]+b0, a[1]+b1);
      *reinterpret_cast<float2*>(p + 8*C_) = make_float2(a[2]+b0, a[3]+b1);
    }
}

// ---------------- softmax: mask + scale + fp16-pair P ------------------------
__global__ __launch_bounds__(256) void softmax_k()
{
  const int gr = blockIdx.x;                 // 0..MT-1
  const int b  = gr >> 12, r = gr & (T_-1);
  const float* src = g_S + ((size_t)b*T_ + r)*T_;
  __half* ph = g_Ph + ((size_t)b*T_ + r)*T_;
  __half* pl = g_Pl + ((size_t)b*T_ + r)*T_;
  const int tid = threadIdx.x;
  const int nv  = r + 1;
  const int kmax = ((r >> 7) + 1) << 7;      // zero-pad to 128 (BK granularity)
  const float scale = 0.03125f;              // 1/sqrt(1024)
  __shared__ float red[256];

  float m = __int_as_float(0xff800000);
  for (int c = tid; c < nv; c += 256) m = fmaxf(m, src[c]);
  red[tid] = m; __syncthreads();
  for (int s = 128; s > 0; s >>= 1){
    if (tid < s) red[tid] = fmaxf(red[tid], red[tid+s]);
    __syncthreads();
  }
  m = red[0]; __syncthreads();

  float sum = 0.f;
  for (int c = tid; c < nv; c += 256) sum += __expf((src[c] - m) * scale);
  red[tid] = sum; __syncthreads();
  for (int s = 128; s > 0; s >>= 1){
    if (tid < s) red[tid] += red[tid+s];
    __syncthreads();
  }
  const float inv = 1.f / red[0];

  for (int c = tid; c < kmax; c += 256){
    float p = (c < nv) ? __expf((src[c] - m) * scale) * inv : 0.f;
    __half h = __float2half_rn(p);
    ph[c] = h;
    pl[c] = __float2half_rn(p - __half2float(h));
  }
}

// ---------------- launch ------------------------------------------------------
extern "C" void kernel_launch(void* const* d_in, const int* in_sizes, int n_in,
                              void* d_out, int out_size)
{
  const float* x  = (const float*)d_in[0];
  const float* Wq = (const float*)d_in[1];
  const float* Wk = (const float*)d_in[2];
  const float* Wv = (const float*)d_in[3];
  const float* Wo = (const float*)d_in[4];
  const float* bo = (const float*)d_in[5];
  float* out = (float*)d_out;
  (void)in_sizes; (void)n_in; (void)out_size;

  cudaFuncSetAttribute(qkv_tc,    cudaFuncAttributeMaxDynamicSharedMemorySize, SMEM_DYN);
  cudaFuncSetAttribute(scores_tc, cudaFuncAttributeMaxDynamicSharedMemorySize, SMEM_DYN);
  cudaFuncSetAttribute(pv_tc,     cudaFuncAttributeMaxDynamicSharedMemorySize, SMEM_DYN);
  cudaFuncSetAttribute(out_tc,    cudaFuncAttributeMaxDynamicSharedMemorySize, SMEM_DYN);

  split_x<<<(size_t)MT_*C_/1024, 256>>>(x);
  conv_w <<<dim3(C_*C_/1024, 4), 256>>>(Wq, Wk, Wv, Wo);

  qkv_tc   <<<dim3(C_/128, MT_/128, 3), 256, SMEM_DYN>>>();
  scores_tc<<<dim3(T_/128, T_/128, B_), 256, SMEM_DYN>>>();
  softmax_k<<<MT_, 256>>>();
  pv_tc    <<<dim3(C_/128, T_/128, B_), 256, SMEM_DYN>>>();
  out_tc   <<<dim3(C_/128, MT_/128, 1), 256, SMEM_DYN>>>(bo, out);
}

// round 10
// speedup vs baseline: 6.4449x; 1.4609x over previous
#include <cuda_runtime.h>
#include <cuda_fp16.h>
#include <cstdint>

#define T_ 4096
#define B_ 4
#define C_ 1024
#define MT_ (B_*T_)
#define SMEM_DYN 99328          // max(3*32KB, 2*48KB) + 1KB align

// ---------------- scratch (device globals; no cudaMalloc allowed) ----------
__device__ __align__(16) __half g_x [(size_t)MT_*C_];           // single fp16
__device__ __align__(16) __half g_W [(size_t)4*C_*C_];          // single fp16
__device__ __align__(16) __half g_Qh[(size_t)MT_*C_], g_Ql[(size_t)MT_*C_];
__device__ __align__(16) __half g_K [(size_t)MT_*C_];           // single
__device__ __align__(16) __half g_Vt[(size_t)MT_*C_];           // single, [B][C][T]
__device__ __align__(16) float  g_S [(size_t)B_*T_*T_];
__device__ __align__(16) __half g_P [(size_t)B_*T_*T_];         // single
__device__ __align__(16) __half g_A [(size_t)MT_*C_];           // single

extern __shared__ char dyn_smem[];

// ---------------- helpers ----------------------------------------------------
static __device__ __forceinline__ uint32_t smem_u32(const void* p){
  uint32_t a;
  asm("{ .reg .u64 t; cvta.to.shared.u64 t, %1; cvt.u32.u64 %0, t; }" : "=r"(a) : "l"(p));
  return a;
}
static __device__ __forceinline__ uint32_t swz(uint32_t o){ return o ^ ((o>>3)&0x70u); }

static __device__ __forceinline__ void ldsm4(uint32_t addr,
    uint32_t &r0, uint32_t &r1, uint32_t &r2, uint32_t &r3){
  asm volatile("ldmatrix.sync.aligned.m8n8.x4.shared.b16 {%0,%1,%2,%3}, [%4];"
    : "=r"(r0), "=r"(r1), "=r"(r2), "=r"(r3) : "r"(addr));
}
static __device__ __forceinline__ void mma16816(float* c,
    const uint32_t* a, const uint32_t* b){
  asm volatile("mma.sync.aligned.m16n8k16.row.col.f32.f16.f16.f32 "
    "{%0,%1,%2,%3}, {%4,%5,%6,%7}, {%8,%9}, {%0,%1,%2,%3};"
    : "+f"(c[0]), "+f"(c[1]), "+f"(c[2]), "+f"(c[3])
    : "r"(a[0]), "r"(a[1]), "r"(a[2]), "r"(a[3]), "r"(b[0]), "r"(b[1]));
}

// 128x64 fp16 tile (16KB) global -> SW128-swizzled smem (256 threads)
static __device__ __forceinline__ void cp_tile(uint32_t sb,
    const __half* __restrict__ g, int ldk){
  const int t = threadIdx.x;
#pragma unroll
  for (int i = 0; i < 4; ++i){
    int q = t + (i<<8);
    int row = q>>3, gr = q&7;
    const __half* src = g + (size_t)row*ldk + (gr<<3);
    uint32_t dst = sb + swz((uint32_t)((row<<7)|(gr<<4)));
    asm volatile("cp.async.cg.shared.global [%0], [%1], 16;"
                 :: "r"(dst), "l"(src) : "memory");
  }
}
// NP=1: [A | B]; NP=2: [Ah | Al | B]
template<int NP>
static __device__ __forceinline__ void cp_stage(uint32_t st,
    const __half* Ah, const __half* Al, int lda,
    const __half* Bs, int ldb, int kt){
  cp_tile(st, Ah + kt, lda);
  if (NP == 2) cp_tile(st + 16384, Al + kt, lda);
  cp_tile(st + NP*16384, Bs + kt, ldb);
}

// ---- core: acc[128,128] += A[128,K] @ (B[128,K])^T, NP-pass A --------------
// 8 warps: wm = wid>>2 (2 x 64 rows), wn = wid&3 (4 x 32 cols); NST-stage pipe
template<int NP, int NST>
static __device__ __forceinline__ void hgemm_core(
    float (&acc)[4][4][4],
    const __half* __restrict__ Ah, const __half* __restrict__ Al, int lda,
    const __half* __restrict__ Bs, int ldb, int K)
{
  constexpr uint32_t STAGE = (uint32_t)(NP+1)*16384u;
  const uint32_t sb = (smem_u32(dyn_smem) + 1023u) & ~1023u;
  const int tid = threadIdx.x, lane = tid&31, wid = tid>>5;
  const int wm = wid>>2, wn = wid&3;
  const int l7 = lane&7, sel = lane>>3;
  const int a_r = l7 + ((sel&1)<<3), a_g = sel>>1;
  const int b_r = l7 + ((sel>>1)<<3), b_g = sel&1;

  const int nc = K >> 6;          // >= 2 everywhere in this pipeline
#pragma unroll
  for (int s = 0; s < NST-1; ++s){
    cp_stage<NP>(sb + (uint32_t)s*STAGE, Ah, Al, lda, Bs, ldb, s<<6);
    asm volatile("cp.async.commit_group;" ::: "memory");
  }

  uint32_t st = sb;
  for (int c = 0; c < nc; ++c){
    if (c + NST-1 < nc){
      cp_stage<NP>(sb + (uint32_t)((c+NST-1)%NST)*STAGE,
                   Ah, Al, lda, Bs, ldb, (c+NST-1)<<6);
      asm volatile("cp.async.commit_group;" ::: "memory");
      if (NST == 3) asm volatile("cp.async.wait_group 2;" ::: "memory");
      else          asm volatile("cp.async.wait_group 1;" ::: "memory");
    } else if (c + 1 < nc){
      asm volatile("cp.async.wait_group 1;" ::: "memory");
    } else {
      asm volatile("cp.async.wait_group 0;" ::: "memory");
    }
    __syncthreads();

#pragma unroll
    for (int ks = 0; ks < 4; ++ks){
      uint32_t bf[4][2];
#pragma unroll
      for (int nn2 = 0; nn2 < 2; ++nn2){
        uint32_t bd = swz((uint32_t)(((wn*32 + nn2*16 + b_r)<<7) | ((ks*2 + b_g)<<4)));
        uint32_t r0, r1, r2, r3;
        ldsm4(st + NP*16384 + bd, r0, r1, r2, r3);
        bf[nn2*2][0]=r0; bf[nn2*2][1]=r1; bf[nn2*2+1][0]=r2; bf[nn2*2+1][1]=r3;
      }
#pragma unroll
      for (int mm = 0; mm < 4; ++mm){
        uint32_t ah[4], al[4];
        uint32_t ad = swz((uint32_t)(((wm*64 + mm*16 + a_r)<<7) | ((ks*2 + a_g)<<4)));
        ldsm4(st + ad, ah[0], ah[1], ah[2], ah[3]);
        if (NP == 2) ldsm4(st + 16384 + ad, al[0], al[1], al[2], al[3]);
#pragma unroll
        for (int nn = 0; nn < 4; ++nn){
          mma16816(acc[mm][nn], ah, bf[nn]);
          if (NP == 2) mma16816(acc[mm][nn], al, bf[nn]);
        }
      }
    }
    if (c + 1 < nc) __syncthreads();
    st += STAGE;
    if (st == sb + (uint32_t)NST*STAGE) st = sb;
  }
}

static __device__ __forceinline__ void pair_store2(
    __half* H, __half* L, size_t idx, float a, float b){
  __half ah = __float2half_rn(a), bh = __float2half_rn(b);
  __half al = __float2half_rn(a - __half2float(ah));
  __half bl = __float2half_rn(b - __half2float(bh));
  *reinterpret_cast<__half2*>(H + idx) = __halves2half2(ah, bh);
  *reinterpret_cast<__half2*>(L + idx) = __halves2half2(al, bl);
}
static __device__ __forceinline__ void h_store2(__half* D, size_t idx, float a, float b){
  *reinterpret_cast<__half2*>(D + idx) =
      __halves2half2(__float2half_rn(a), __float2half_rn(b));
}

// ---------------- input converters ------------------------------------------
__global__ __launch_bounds__(256) void conv_x(const float* __restrict__ x){
  size_t i = ((size_t)blockIdx.x*256 + threadIdx.x)*4;
  float4 v = *reinterpret_cast<const float4*>(x + i);
  reinterpret_cast<__half2*>(g_x + i)[0] = __halves2half2(__float2half_rn(v.x), __float2half_rn(v.y));
  reinterpret_cast<__half2*>(g_x + i)[1] = __halves2half2(__float2half_rn(v.z), __float2half_rn(v.w));
}
__global__ __launch_bounds__(256) void conv_w(
    const float* __restrict__ Wq, const float* __restrict__ Wk,
    const float* __restrict__ Wv, const float* __restrict__ Wo)
{
  const int z = blockIdx.y;
  const float* src = (z==0)?Wq:(z==1)?Wk:(z==2)?Wv:Wo;
  size_t i = ((size_t)blockIdx.x*256 + threadIdx.x)*4;
  float4 v = *reinterpret_cast<const float4*>(src + i);
  __half* dst = g_W + (size_t)z*C_*C_ + i;
  reinterpret_cast<__half2*>(dst)[0] = __halves2half2(__float2half_rn(v.x), __float2half_rn(v.y));
  reinterpret_cast<__half2*>(dst)[1] = __halves2half2(__float2half_rn(v.z), __float2half_rn(v.w));
}

// ---------------- GEMM kernels ------------------------------------------------
__global__ __launch_bounds__(256, 2) void qkv_tc()
{
  const int z = blockIdx.z, m0 = blockIdx.y<<7, n0 = blockIdx.x<<7;
  float acc[4][4][4] = {};
  hgemm_core<1,3>(acc, g_x + (size_t)m0*C_, nullptr, C_,
                  g_W + (size_t)z*C_*C_ + (size_t)n0*C_, C_, C_);

  const int lane = threadIdx.x&31, wid = threadIdx.x>>5;
  const int wm = wid>>2, wn = wid&3;
  const int rb = lane>>2, cb = (lane&3)*2;

  if (z == 2){
    // V: transpose in smem to [c][t] fp16, then coalesced writes
    __syncthreads();
    __half* sf = reinterpret_cast<__half*>(dyn_smem);   // 128x128 half = 32KB
#pragma unroll
    for (int mm = 0; mm < 4; ++mm)
#pragma unroll
      for (int nn = 0; nn < 4; ++nn){
        const int tl = wm*64 + mm*16 + rb;
        const int cl = wn*32 + nn*8 + cb;
        const float* a = acc[mm][nn];
#pragma unroll
        for (int u = 0; u < 4; ++u){
          const int tt = tl + (u>>1)*8;
          const int ccl = cl + (u&1);
          sf[ccl*128 + tt] = __float2half_rn(a[u]);
        }
      }
    __syncthreads();
    const int b = m0 >> 12, ml0 = m0 & (T_-1);
    for (int i = threadIdx.x; i < 2048; i += 256){   // 128 rows x 16 uint4
      const int row = i>>4, c4 = i&15;
      reinterpret_cast<uint4*>(g_Vt + (size_t)(b*C_ + n0 + row)*T_ + ml0)[c4] =
          reinterpret_cast<const uint4*>(sf + row*128)[c4];
    }
    return;
  }

#pragma unroll
  for (int mm = 0; mm < 4; ++mm)
#pragma unroll
    for (int nn = 0; nn < 4; ++nn){
      const int r  = m0 + wm*64 + mm*16 + rb;
      const int cc = n0 + wn*32 + nn*8 + cb;
      const float* a = acc[mm][nn];
      size_t base = (size_t)r*C_ + cc;
      if (z == 0){
        pair_store2(g_Qh, g_Ql, base,        a[0], a[1]);
        pair_store2(g_Qh, g_Ql, base + 8*C_, a[2], a[3]);
      } else {
        h_store2(g_K, base,        a[0], a[1]);
        h_store2(g_K, base + 8*C_, a[2], a[3]);
      }
    }
}

__global__ __launch_bounds__(256, 2) void scores_tc()
{
  if (blockIdx.x > blockIdx.y) return;               // fully-masked tile
  const int bz = blockIdx.z, m0 = blockIdx.y<<7, n0 = blockIdx.x<<7;
  const size_t qb = ((size_t)bz*T_ + m0)*C_;
  const size_t kb = ((size_t)bz*T_ + n0)*C_;
  float acc[4][4][4] = {};
  hgemm_core<2,2>(acc, g_Qh + qb, g_Ql + qb, C_, g_K + kb, C_, C_);

  const int lane = threadIdx.x&31, wid = threadIdx.x>>5;
  const int wm = wid>>2, wn = wid&3;
  const int rb = lane>>2, cb = (lane&3)*2;
#pragma unroll
  for (int mm = 0; mm < 4; ++mm)
#pragma unroll
    for (int nn = 0; nn < 4; ++nn){
      const int r  = m0 + wm*64 + mm*16 + rb;
      const int cc = n0 + wn*32 + nn*8 + cb;
      const float* a = acc[mm][nn];
      float* p = g_S + ((size_t)bz*T_ + r)*T_ + cc;
      *reinterpret_cast<float2*>(p)           = make_float2(a[0], a[1]);
      *reinterpret_cast<float2*>(p + 8ull*T_) = make_float2(a[2], a[3]);
    }
}

__global__ __launch_bounds__(256, 2) void pv_tc()
{
  const int bz = blockIdx.z, m0 = blockIdx.y<<7, n0 = blockIdx.x<<7;
  const int K  = m0 + 128;
  const size_t pb = ((size_t)bz*T_ + m0)*T_;
  const size_t vb = ((size_t)bz*C_ + n0)*T_;
  float acc[4][4][4] = {};
  hgemm_core<1,3>(acc, g_P + pb, nullptr, T_, g_Vt + vb, T_, K);

  const int lane = threadIdx.x&31, wid = threadIdx.x>>5;
  const int wm = wid>>2, wn = wid&3;
  const int rb = lane>>2, cb = (lane&3)*2;
#pragma unroll
  for (int mm = 0; mm < 4; ++mm)
#pragma unroll
    for (int nn = 0; nn < 4; ++nn){
      const int r  = m0 + wm*64 + mm*16 + rb;
      const int cc = n0 + wn*32 + nn*8 + cb;
      const float* a = acc[mm][nn];
      size_t base = ((size_t)bz*T_ + r)*C_ + cc;
      h_store2(g_A, base,        a[0], a[1]);
      h_store2(g_A, base + 8*C_, a[2], a[3]);
    }
}

__global__ __launch_bounds__(256, 2) void out_tc(const float* __restrict__ bo,
                                                 float* __restrict__ out)
{
  const int m0 = blockIdx.y<<7, n0 = blockIdx.x<<7;
  float acc[4][4][4] = {};
  hgemm_core<1,3>(acc, g_A + (size_t)m0*C_, nullptr, C_,
                  g_W + (size_t)3*C_*C_ + (size_t)n0*C_, C_, C_);

  const int lane = threadIdx.x&31, wid = threadIdx.x>>5;
  const int wm = wid>>2, wn = wid&3;
  const int rb = lane>>2, cb = (lane&3)*2;
#pragma unroll
  for (int mm = 0; mm < 4; ++mm)
#pragma unroll
    for (int nn = 0; nn < 4; ++nn){
      const int r  = m0 + wm*64 + mm*16 + rb;
      const int cc = n0 + wn*32 + nn*8 + cb;
      const float* a = acc[mm][nn];
      const float b0 = bo[cc], b1 = bo[cc+1];
      float* p = out + (size_t)r*C_ + cc;
      *reinterpret_cast<float2*>(p)        = make_float2(a[0]+b0, a[1]+b1);
      *reinterpret_cast<float2*>(p + 8*C_) = make_float2(a[2]+b0, a[3]+b1);
    }
}

// ---------------- softmax: mask + scale + single fp16 P ----------------------
__global__ __launch_bounds__(256) void softmax_k()
{
  const int gr = blockIdx.x;                 // 0..MT-1
  const int b  = gr >> 12, r = gr & (T_-1);
  const float* src = g_S + ((size_t)b*T_ + r)*T_;
  __half* ph = g_P + ((size_t)b*T_ + r)*T_;
  const int tid = threadIdx.x;
  const int nv  = r + 1;
  const int kmax = ((r >> 7) + 1) << 7;      // zero-pad to 128 (BK granularity)
  const float scale = 0.03125f;              // 1/sqrt(1024)
  __shared__ float red[256];

  float m = __int_as_float(0xff800000);
  for (int c = tid; c < nv; c += 256) m = fmaxf(m, src[c]);
  red[tid] = m; __syncthreads();
  for (int s = 128; s > 0; s >>= 1){
    if (tid < s) red[tid] = fmaxf(red[tid], red[tid+s]);
    __syncthreads();
  }
  m = red[0]; __syncthreads();

  float sum = 0.f;
  for (int c = tid; c < nv; c += 256) sum += __expf((src[c] - m) * scale);
  red[tid] = sum; __syncthreads();
  for (int s = 128; s > 0; s >>= 1){
    if (tid < s) red[tid] += red[tid+s];
    __syncthreads();
  }
  const float inv = 1.f / red[0];

  for (int c = tid; c < kmax; c += 256){
    float p = (c < nv) ? __expf((src[c] - m) * scale) * inv : 0.f;
    ph[c] = __float2half_rn(p);
  }
}

// ---------------- launch ------------------------------------------------------
extern "C" void kernel_launch(void* const* d_in, const int* in_sizes, int n_in,
                              void* d_out, int out_size)
{
  const float* x  = (const float*)d_in[0];
  const float* Wq = (const float*)d_in[1];
  const float* Wk = (const float*)d_in[2];
  const float* Wv = (const float*)d_in[3];
  const float* Wo = (const float*)d_in[4];
  const float* bo = (const float*)d_in[5];
  float* out = (float*)d_out;
  (void)in_sizes; (void)n_in; (void)out_size;

  cudaFuncSetAttribute(qkv_tc,    cudaFuncAttributeMaxDynamicSharedMemorySize, SMEM_DYN);
  cudaFuncSetAttribute(scores_tc, cudaFuncAttributeMaxDynamicSharedMemorySize, SMEM_DYN);
  cudaFuncSetAttribute(pv_tc,     cudaFuncAttributeMaxDynamicSharedMemorySize, SMEM_DYN);
  cudaFuncSetAttribute(out_tc,    cudaFuncAttributeMaxDynamicSharedMemorySize, SMEM_DYN);

  conv_x<<<(size_t)MT_*C_/1024, 256>>>(x);
  conv_w<<<dim3(C_*C_/1024, 4), 256>>>(Wq, Wk, Wv, Wo);

  qkv_tc   <<<dim3(C_/128, MT_/128, 3), 256, SMEM_DYN>>>();
  scores_tc<<<dim3(T_/128, T_/128, B_), 256, SMEM_DYN>>>();
  softmax_k<<<MT_, 256>>>();
  pv_tc    <<<dim3(C_/128, T_/128, B_), 256, SMEM_DYN>>>();
  out_tc   <<<dim3(C_/128, MT_/128, 1), 256, SMEM_DYN>>>(bo, out);
}

// round 11
// speedup vs baseline: 7.7384x; 1.2007x over previous
#include <cuda_runtime.h>
#include <cuda_fp16.h>
#include <cstdint>

#define T_ 4096
#define B_ 4
#define C_ 1024
#define MT_ (B_*T_)
#define SMEM_DYN 99328          // 3 stages x 32KB + 1KB align

// ---------------- scratch (device globals; no cudaMalloc allowed) ----------
__device__ __align__(16) __half g_x [(size_t)MT_*C_];           // single fp16
__device__ __align__(16) __half g_W [(size_t)4*C_*C_];          // single fp16
__device__ __align__(16) __half g_Q [(size_t)MT_*C_];           // single
__device__ __align__(16) __half g_K [(size_t)MT_*C_];           // single
__device__ __align__(16) __half g_Vt[(size_t)MT_*C_];           // single, [B][C][T]
__device__ __align__(16) float  g_S [(size_t)B_*T_*T_];
__device__ __align__(16) __half g_P [(size_t)B_*T_*T_];         // single
__device__ __align__(16) __half g_A [(size_t)MT_*C_];           // single

extern __shared__ char dyn_smem[];

// ---------------- helpers ----------------------------------------------------
static __device__ __forceinline__ uint32_t smem_u32(const void* p){
  uint32_t a;
  asm("{ .reg .u64 t; cvta.to.shared.u64 t, %1; cvt.u32.u64 %0, t; }" : "=r"(a) : "l"(p));
  return a;
}
static __device__ __forceinline__ uint32_t swz(uint32_t o){ return o ^ ((o>>3)&0x70u); }

static __device__ __forceinline__ void ldsm4(uint32_t addr,
    uint32_t &r0, uint32_t &r1, uint32_t &r2, uint32_t &r3){
  asm volatile("ldmatrix.sync.aligned.m8n8.x4.shared.b16 {%0,%1,%2,%3}, [%4];"
    : "=r"(r0), "=r"(r1), "=r"(r2), "=r"(r3) : "r"(addr));
}
static __device__ __forceinline__ void mma16816(float* c,
    const uint32_t* a, const uint32_t* b){
  asm volatile("mma.sync.aligned.m16n8k16.row.col.f32.f16.f16.f32 "
    "{%0,%1,%2,%3}, {%4,%5,%6,%7}, {%8,%9}, {%0,%1,%2,%3};"
    : "+f"(c[0]), "+f"(c[1]), "+f"(c[2]), "+f"(c[3])
    : "r"(a[0]), "r"(a[1]), "r"(a[2]), "r"(a[3]), "r"(b[0]), "r"(b[1]));
}

// 128x64 fp16 tile (16KB) global -> SW128-swizzled smem (256 threads)
static __device__ __forceinline__ void cp_tile(uint32_t sb,
    const __half* __restrict__ g, int ldk){
  const int t = threadIdx.x;
#pragma unroll
  for (int i = 0; i < 4; ++i){
    int q = t + (i<<8);
    int row = q>>3, gr = q&7;
    const __half* src = g + (size_t)row*ldk + (gr<<3);
    uint32_t dst = sb + swz((uint32_t)((row<<7)|(gr<<4)));
    asm volatile("cp.async.cg.shared.global [%0], [%1], 16;"
                 :: "r"(dst), "l"(src) : "memory");
  }
}
static __device__ __forceinline__ void cp_stage(uint32_t st,
    const __half* As, int lda, const __half* Bs, int ldb, int kt){
  cp_tile(st,         As + kt, lda);
  cp_tile(st + 16384, Bs + kt, ldb);
}

// ---- core: acc[128,128] += A[128,K] @ (B[128,K])^T, single-pass fp16 -------
// 8 warps: wm = wid>>2 (2 x 64 rows), wn = wid&3 (4 x 32 cols); 3-stage pipe
static __device__ __forceinline__ void hgemm_core(
    float (&acc)[4][4][4],
    const __half* __restrict__ As, int lda,
    const __half* __restrict__ Bs, int ldb, int K)
{
  constexpr uint32_t STAGE = 32768u;
  const uint32_t sb = (smem_u32(dyn_smem) + 1023u) & ~1023u;
  const int tid = threadIdx.x, lane = tid&31, wid = tid>>5;
  const int wm = wid>>2, wn = wid&3;
  const int l7 = lane&7, sel = lane>>3;
  const int a_r = l7 + ((sel&1)<<3), a_g = sel>>1;
  const int b_r = l7 + ((sel>>1)<<3), b_g = sel&1;

  const int nc = K >> 6;          // >= 2 everywhere in this pipeline
  cp_stage(sb,         As, lda, Bs, ldb, 0);
  asm volatile("cp.async.commit_group;" ::: "memory");
  cp_stage(sb + STAGE, As, lda, Bs, ldb, 64);
  asm volatile("cp.async.commit_group;" ::: "memory");

  uint32_t st = sb;
  for (int c = 0; c < nc; ++c){
    if (c + 2 < nc){
      cp_stage(sb + (uint32_t)((c+2)%3)*STAGE, As, lda, Bs, ldb, (c+2)<<6);
      asm volatile("cp.async.commit_group;" ::: "memory");
      asm volatile("cp.async.wait_group 2;" ::: "memory");
    } else if (c + 1 < nc){
      asm volatile("cp.async.wait_group 1;" ::: "memory");
    } else {
      asm volatile("cp.async.wait_group 0;" ::: "memory");
    }
    __syncthreads();

#pragma unroll
    for (int ks = 0; ks < 4; ++ks){
      uint32_t bf[4][2];
#pragma unroll
      for (int nn2 = 0; nn2 < 2; ++nn2){
        uint32_t bd = swz((uint32_t)(((wn*32 + nn2*16 + b_r)<<7) | ((ks*2 + b_g)<<4)));
        uint32_t r0, r1, r2, r3;
        ldsm4(st + 16384 + bd, r0, r1, r2, r3);
        bf[nn2*2][0]=r0; bf[nn2*2][1]=r1; bf[nn2*2+1][0]=r2; bf[nn2*2+1][1]=r3;
      }
#pragma unroll
      for (int mm = 0; mm < 4; ++mm){
        uint32_t ah[4];
        uint32_t ad = swz((uint32_t)(((wm*64 + mm*16 + a_r)<<7) | ((ks*2 + a_g)<<4)));
        ldsm4(st + ad, ah[0], ah[1], ah[2], ah[3]);
#pragma unroll
        for (int nn = 0; nn < 4; ++nn)
          mma16816(acc[mm][nn], ah, bf[nn]);
      }
    }
    if (c + 1 < nc) __syncthreads();
    st += STAGE;
    if (st == sb + 3u*STAGE) st = sb;
  }
}

static __device__ __forceinline__ void h_store2(__half* D, size_t idx, float a, float b){
  *reinterpret_cast<__half2*>(D + idx) =
      __halves2half2(__float2half_rn(a), __float2half_rn(b));
}

// ---------------- input converters ------------------------------------------
__global__ __launch_bounds__(256) void conv_x(const float* __restrict__ x){
  size_t i = ((size_t)blockIdx.x*256 + threadIdx.x)*4;
  float4 v = *reinterpret_cast<const float4*>(x + i);
  reinterpret_cast<__half2*>(g_x + i)[0] = __halves2half2(__float2half_rn(v.x), __float2half_rn(v.y));
  reinterpret_cast<__half2*>(g_x + i)[1] = __halves2half2(__float2half_rn(v.z), __float2half_rn(v.w));
}
__global__ __launch_bounds__(256) void conv_w(
    const float* __restrict__ Wq, const float* __restrict__ Wk,
    const float* __restrict__ Wv, const float* __restrict__ Wo)
{
  const int z = blockIdx.y;
  const float* src = (z==0)?Wq:(z==1)?Wk:(z==2)?Wv:Wo;
  size_t i = ((size_t)blockIdx.x*256 + threadIdx.x)*4;
  float4 v = *reinterpret_cast<const float4*>(src + i);
  __half* dst = g_W + (size_t)z*C_*C_ + i;
  reinterpret_cast<__half2*>(dst)[0] = __halves2half2(__float2half_rn(v.x), __float2half_rn(v.y));
  reinterpret_cast<__half2*>(dst)[1] = __halves2half2(__float2half_rn(v.z), __float2half_rn(v.w));
}

// ---------------- GEMM kernels ------------------------------------------------
__global__ __launch_bounds__(256, 2) void qkv_tc()
{
  const int z = blockIdx.z, m0 = blockIdx.y<<7, n0 = blockIdx.x<<7;
  float acc[4][4][4] = {};
  hgemm_core(acc, g_x + (size_t)m0*C_, C_,
             g_W + (size_t)z*C_*C_ + (size_t)n0*C_, C_, C_);

  const int lane = threadIdx.x&31, wid = threadIdx.x>>5;
  const int wm = wid>>2, wn = wid&3;
  const int rb = lane>>2, cb = (lane&3)*2;

  if (z == 2){
    // V: transpose in smem to [c][t] fp16, then coalesced writes
    __syncthreads();
    __half* sf = reinterpret_cast<__half*>(dyn_smem);   // 128x128 half = 32KB
#pragma unroll
    for (int mm = 0; mm < 4; ++mm)
#pragma unroll
      for (int nn = 0; nn < 4; ++nn){
        const int tl = wm*64 + mm*16 + rb;
        const int cl = wn*32 + nn*8 + cb;
        const float* a = acc[mm][nn];
#pragma unroll
        for (int u = 0; u < 4; ++u){
          const int tt = tl + (u>>1)*8;
          const int ccl = cl + (u&1);
          sf[ccl*128 + tt] = __float2half_rn(a[u]);
        }
      }
    __syncthreads();
    const int b = m0 >> 12, ml0 = m0 & (T_-1);
    for (int i = threadIdx.x; i < 2048; i += 256){   // 128 rows x 16 uint4
      const int row = i>>4, c4 = i&15;
      reinterpret_cast<uint4*>(g_Vt + (size_t)(b*C_ + n0 + row)*T_ + ml0)[c4] =
          reinterpret_cast<const uint4*>(sf + row*128)[c4];
    }
    return;
  }

  __half* D = (z == 0) ? g_Q : g_K;
#pragma unroll
  for (int mm = 0; mm < 4; ++mm)
#pragma unroll
    for (int nn = 0; nn < 4; ++nn){
      const int r  = m0 + wm*64 + mm*16 + rb;
      const int cc = n0 + wn*32 + nn*8 + cb;
      const float* a = acc[mm][nn];
      size_t base = (size_t)r*C_ + cc;
      h_store2(D, base,        a[0], a[1]);
      h_store2(D, base + 8*C_, a[2], a[3]);
    }
}

__global__ __launch_bounds__(256, 2) void scores_tc()
{
  if (blockIdx.x > blockIdx.y) return;               // fully-masked tile
  const int bz = blockIdx.z, m0 = blockIdx.y<<7, n0 = blockIdx.x<<7;
  const size_t qb = ((size_t)bz*T_ + m0)*C_;
  const size_t kb = ((size_t)bz*T_ + n0)*C_;
  float acc[4][4][4] = {};
  hgemm_core(acc, g_Q + qb, C_, g_K + kb, C_, C_);

  const int lane = threadIdx.x&31, wid = threadIdx.x>>5;
  const int wm = wid>>2, wn = wid&3;
  const int rb = lane>>2, cb = (lane&3)*2;
#pragma unroll
  for (int mm = 0; mm < 4; ++mm)
#pragma unroll
    for (int nn = 0; nn < 4; ++nn){
      const int r  = m0 + wm*64 + mm*16 + rb;
      const int cc = n0 + wn*32 + nn*8 + cb;
      const float* a = acc[mm][nn];
      float* p = g_S + ((size_t)bz*T_ + r)*T_ + cc;
      *reinterpret_cast<float2*>(p)           = make_float2(a[0], a[1]);
      *reinterpret_cast<float2*>(p + 8ull*T_) = make_float2(a[2], a[3]);
    }
}

__global__ __launch_bounds__(256, 2) void pv_tc()
{
  const int bz = blockIdx.z, m0 = blockIdx.y<<7, n0 = blockIdx.x<<7;
  const int K  = m0 + 128;
  const size_t pb = ((size_t)bz*T_ + m0)*T_;
  const size_t vb = ((size_t)bz*C_ + n0)*T_;
  float acc[4][4][4] = {};
  hgemm_core(acc, g_P + pb, T_, g_Vt + vb, T_, K);

  const int lane = threadIdx.x&31, wid = threadIdx.x>>5;
  const int wm = wid>>2, wn = wid&3;
  const int rb = lane>>2, cb = (lane&3)*2;
#pragma unroll
  for (int mm = 0; mm < 4; ++mm)
#pragma unroll
    for (int nn = 0; nn < 4; ++nn){
      const int r  = m0 + wm*64 + mm*16 + rb;
      const int cc = n0 + wn*32 + nn*8 + cb;
      const float* a = acc[mm][nn];
      size_t base = ((size_t)bz*T_ + r)*C_ + cc;
      h_store2(g_A, base,        a[0], a[1]);
      h_store2(g_A, base + 8*C_, a[2], a[3]);
    }
}

__global__ __launch_bounds__(256, 2) void out_tc(const float* __restrict__ bo,
                                                 float* __restrict__ out)
{
  const int m0 = blockIdx.y<<7, n0 = blockIdx.x<<7;
  float acc[4][4][4] = {};
  hgemm_core(acc, g_A + (size_t)m0*C_, C_,
             g_W + (size_t)3*C_*C_ + (size_t)n0*C_, C_, C_);

  const int lane = threadIdx.x&31, wid = threadIdx.x>>5;
  const int wm = wid>>2, wn = wid&3;
  const int rb = lane>>2, cb = (lane&3)*2;
#pragma unroll
  for (int mm = 0; mm < 4; ++mm)
#pragma unroll
    for (int nn = 0; nn < 4; ++nn){
      const int r  = m0 + wm*64 + mm*16 + rb;
      const int cc = n0 + wn*32 + nn*8 + cb;
      const float* a = acc[mm][nn];
      const float b0 = bo[cc], b1 = bo[cc+1];
      float* p = out + (size_t)r*C_ + cc;
      *reinterpret_cast<float2*>(p)        = make_float2(a[0]+b0, a[1]+b1);
      *reinterpret_cast<float2*>(p + 8*C_) = make_float2(a[2]+b0, a[3]+b1);
    }
}

// ---------------- softmax: single-read, register-resident row ----------------
__global__ __launch_bounds__(256) void softmax_k()
{
  const int gr = blockIdx.x;                 // 0..MT-1
  const int b  = gr >> 12, r = gr & (T_-1);
  const float* src = g_S + ((size_t)b*T_ + r)*T_;
  __half* ph = g_P + ((size_t)b*T_ + r)*T_;
  const int tid = threadIdx.x;
  const int nv  = r + 1;
  const int kmax = ((r >> 7) + 1) << 7;      // zero-pad to 128 (BK granularity)
  const float scale = 0.03125f;              // 1/sqrt(1024)
  const float NINF = __int_as_float(0xff800000);
  __shared__ float red[256];

  float v[16];
  float m = NINF;
#pragma unroll
  for (int i = 0; i < 16; ++i){
    const int c = tid + (i<<8);
    v[i] = (c < nv) ? src[c] : NINF;
    m = fmaxf(m, v[i]);
  }
  red[tid] = m; __syncthreads();
  for (int s = 128; s > 0; s >>= 1){
    if (tid < s) red[tid] = fmaxf(red[tid], red[tid+s]);
    __syncthreads();
  }
  m = red[0]; __syncthreads();

  float sum = 0.f;
#pragma unroll
  for (int i = 0; i < 16; ++i){
    v[i] = __expf((v[i] - m) * scale);       // exp(-inf) = 0 for masked cols
    sum += v[i];
  }
  red[tid] = sum; __syncthreads();
  for (int s = 128; s > 0; s >>= 1){
    if (tid < s) red[tid] += red[tid+s];
    __syncthreads();
  }
  const float inv = 1.f / red[0];

#pragma unroll
  for (int i = 0; i < 16; ++i){
    const int c = tid + (i<<8);
    if (c < kmax) ph[c] = __float2half_rn(v[i] * inv);
  }
}

// ---------------- launch ------------------------------------------------------
extern "C" void kernel_launch(void* const* d_in, const int* in_sizes, int n_in,
                              void* d_out, int out_size)
{
  const float* x  = (const float*)d_in[0];
  const float* Wq = (const float*)d_in[1];
  const float* Wk = (const float*)d_in[2];
  const float* Wv = (const float*)d_in[3];
  const float* Wo = (const float*)d_in[4];
  const float* bo = (const float*)d_in[5];
  float* out = (float*)d_out;
  (void)in_sizes; (void)n_in; (void)out_size;

  cudaFuncSetAttribute(qkv_tc,    cudaFuncAttributeMaxDynamicSharedMemorySize, SMEM_DYN);
  cudaFuncSetAttribute(scores_tc, cudaFuncAttributeMaxDynamicSharedMemorySize, SMEM_DYN);
  cudaFuncSetAttribute(pv_tc,     cudaFuncAttributeMaxDynamicSharedMemorySize, SMEM_DYN);
  cudaFuncSetAttribute(out_tc,    cudaFuncAttributeMaxDynamicSharedMemorySize, SMEM_DYN);

  conv_x<<<(size_t)MT_*C_/1024, 256>>>(x);
  conv_w<<<dim3(C_*C_/1024, 4), 256>>>(Wq, Wk, Wv, Wo);

  qkv_tc   <<<dim3(C_/128, MT_/128, 3), 256, SMEM_DYN>>>();
  scores_tc<<<dim3(T_/128, T_/128, B_), 256, SMEM_DYN>>>();
  softmax_k<<<MT_, 256>>>();
  pv_tc    <<<dim3(C_/128, T_/128, B_), 256, SMEM_DYN>>>();
  out_tc   <<<dim3(C_/128, MT_/128, 1), 256, SMEM_DYN>>>(bo, out);
}